// round 6
// baseline (speedup 1.0000x reference)
#include <cuda_runtime.h>

// Problem constants
#define BATCH   16384
#define T_IN    60
#define I_DIM   32
#define H_DIM   128
#define SEQ     30
#define STEPS   30
#define N3      384      // 3*H gate rows
#define K_TOT   160      // fused K: 32 (x part) + 128 (h part)
#define TM      64       // batch rows per CTA
#define NTHR    512
#define KC      32       // k-chunk staged per buffer
#define NCH     5        // K_TOT / KC
#define SS      68       // state row stride in floats (64 + pad, 16B aligned)
#define CHUNK_F (KC*N3)  // 12288 floats per weight chunk

#define SMEM_FLOATS (K_TOT*SS + 2*CHUNK_F + H_DIM*I_DIM)
#define SMEM_BYTES  (SMEM_FLOATS*4)

typedef unsigned long long ull;

// Fused, k-major weight matrix: g_W[k][j], k<32 -> W_ih[j][k], else W_hh[j][k-32]
__device__ float g_W[K_TOT*N3];

__global__ void prep_kernel(const float* __restrict__ Wih,
                            const float* __restrict__ Whh){
    int idx = blockIdx.x*blockDim.x + threadIdx.x;
    if (idx < K_TOT*N3){
        int k = idx / N3, j = idx - k*N3;
        g_W[idx] = (k < I_DIM) ? Wih[j*I_DIM + k] : Whh[j*H_DIM + (k - I_DIM)];
    }
}

__device__ __forceinline__ void cp16(float* sdst, const float* gsrc){
    unsigned sa = (unsigned)__cvta_generic_to_shared(sdst);
    asm volatile("cp.async.cg.shared.global [%0], [%1], 16;\n" :: "r"(sa), "l"(gsrc));
}
__device__ __forceinline__ void cp_commit(){ asm volatile("cp.async.commit_group;\n"); }
__device__ __forceinline__ void cp_wait_all(){ asm volatile("cp.async.wait_all;\n"); }

__device__ __forceinline__ void stage(float* dst, const float* src, int tid){
    #pragma unroll
    for (int r = 0; r < CHUNK_F/4/NTHR; r++){   // 6 x 16B per thread
        int o = (tid + r*NTHR)*4;
        cp16(dst + o, src + o);
    }
}

// ---- packed fp32x2 helpers (bit-exact IEEE fp32 lanes) ----
__device__ __forceinline__ ull pk2(float lo, float hi){
    ull r; asm("mov.b64 %0, {%1, %2};" : "=l"(r) : "f"(lo), "f"(hi)); return r;
}
__device__ __forceinline__ void upk2(float& lo, float& hi, ull v){
    asm("mov.b64 {%0, %1}, %2;" : "=f"(lo), "=f"(hi) : "l"(v));
}
__device__ __forceinline__ void ffma2(ull& d, ull a, ull b){
    asm("fma.rn.f32x2 %0, %1, %2, %0;" : "+l"(d) : "l"(a), "l"(b));
}

__device__ __forceinline__ float sigm(float v){
    return __fdividef(1.f, 1.f + __expf(-v));
}
__device__ __forceinline__ float tanh_f(float v){
    float e = __expf(-2.f*fabsf(v));            // in (0,1], no overflow
    float t = __fdividef(1.f - e, 1.f + e);
    return v < 0.f ? -t : t;
}

// One 32-k slice of the gate GEMM using packed f32x2 FMAs.
// Accumulators are j-pairs: a[mi][jp] covers gate columns (jt*4+2*jp, jt*4+2*jp+1).
__device__ __forceinline__ void kloop(ull (&ar)[4][2], ull (&az)[4][2],
                                      ull (&an)[4][2],
                                      const float* __restrict__ wb,
                                      const float* __restrict__ st,
                                      int mt, int jt){
    #pragma unroll 4
    for (int k = 0; k < KC; k++){
        const float4 a0 = *(const float4*)(st + k*SS + mt*4);
        ull sp[4];
        sp[0] = pk2(a0.x, a0.x); sp[1] = pk2(a0.y, a0.y);
        sp[2] = pk2(a0.z, a0.z); sp[3] = pk2(a0.w, a0.w);
        // weights as 16B vectors -> natural b64 register pairs, no repack
        const ulonglong2* w2 = (const ulonglong2*)(wb + k*N3);
        ulonglong2 wr = w2[jt], wz = w2[32+jt], wn = w2[64+jt];
        #pragma unroll
        for (int mi = 0; mi < 4; mi++){
            ffma2(ar[mi][0], sp[mi], wr.x);
            ffma2(ar[mi][1], sp[mi], wr.y);
            ffma2(az[mi][0], sp[mi], wz.x);
            ffma2(az[mi][1], sp[mi], wz.y);
            ffma2(an[mi][0], sp[mi], wn.x);
            ffma2(an[mi][1], sp[mi], wn.y);
        }
    }
}

__global__ __launch_bounds__(NTHR, 1)
void gru_kernel(const float* __restrict__ x, const float* __restrict__ h0,
                const float* __restrict__ bih, const float* __restrict__ bhh,
                const float* __restrict__ Wout, const float* __restrict__ bout,
                float* __restrict__ out){
    extern __shared__ float sm[];
    float* s_state = sm;                    // [160][SS]: rows 0..31 = x, 32..159 = h
    float* s_w     = sm + K_TOT*SS;         // [2][KC][384] weight slices
    float* s_wout  = s_w + 2*CHUNK_F;       // [128][32]  W_out^T

    const int tid = threadIdx.x;
    const int m0  = blockIdx.x * TM;
    const int mt  = tid & 15;               // 16 m-tiles of 4 rows
    const int jt  = tid >> 4;               // 32 j-threads of 4 gate cols

    // ---- init state (transposed [k][m]) ----
    for (int idx = tid; idx < TM*I_DIM; idx += NTHR){
        int m = idx >> 5, i = idx & 31;
        s_state[i*SS + m] = x[((m0+m)*T_IN + SEQ)*I_DIM + i];
    }
    for (int idx = tid; idx < TM*H_DIM; idx += NTHR){
        int m = idx >> 7, k = idx & 127;
        s_state[(I_DIM+k)*SS + m] = h0[(m0+m)*H_DIM + k];
    }
    for (int idx = tid; idx < H_DIM*I_DIM; idx += NTHR){
        int i = idx & 31, k = idx >> 5;
        s_wout[k*I_DIM + i] = Wout[i*H_DIM + k];
    }

    // biases hoisted to registers (constant over t)
    float br[4], bz[4], bnx[4], bnh[4];
    #pragma unroll
    for (int ji = 0; ji < 4; ji++){
        int j = jt*4 + ji;
        br[ji]  = __ldg(bih + j)        + __ldg(bhh + j);
        bz[ji]  = __ldg(bih + H_DIM+j)  + __ldg(bhh + H_DIM+j);
        bnx[ji] = __ldg(bih + 2*H_DIM+j);
        bnh[ji] = __ldg(bhh + 2*H_DIM+j);
    }
    const float bo = __ldg(bout + (tid & 31));

    // prologue: chunk 0 -> buffer 0
    stage(s_w, g_W, tid);
    cp_commit(); cp_wait_all();
    __syncthreads();

    int cur = 0;
    for (int t = 0; t < STEPS; t++){
        ull ar2[4][2] = {}, az2[4][2] = {}, anx2[4][2] = {}, anh2[4][2] = {};

        for (int c = 0; c < NCH; c++){
            int nc = c + 1; if (nc == NCH) nc = 0;   // wraps to chunk 0 for next t
            stage(s_w + (cur^1)*CHUNK_F, g_W + nc*CHUNK_F, tid);
            cp_commit();
            const float* wb = s_w + cur*CHUNK_F;
            const float* st = s_state + c*KC*SS;
            if (c == 0) kloop(ar2, az2, anx2, wb, st, mt, jt);   // x-part of n
            else        kloop(ar2, az2, anh2, wb, st, mt, jt);   // h-part of n
            cp_wait_all();
            __syncthreads();
            cur ^= 1;
        }

        // ---- unpack accumulators ----
        float ar[4][4], az[4][4], anx[4][4], anh[4][4];
        #pragma unroll
        for (int mi = 0; mi < 4; mi++){
            #pragma unroll
            for (int jp = 0; jp < 2; jp++){
                upk2(ar[mi][2*jp],  ar[mi][2*jp+1],  ar2[mi][jp]);
                upk2(az[mi][2*jp],  az[mi][2*jp+1],  az2[mi][jp]);
                upk2(anx[mi][2*jp], anx[mi][2*jp+1], anx2[mi][jp]);
                upk2(anh[mi][2*jp], anh[mi][2*jp+1], anh2[mi][jp]);
            }
        }

        // ---- gates + h update (exclusive (m,j) ownership per thread) ----
        #pragma unroll
        for (int ji = 0; ji < 4; ji++){
            int j = jt*4 + ji;
            float* hrow = s_state + (I_DIM+j)*SS + mt*4;
            float4 hv = *(float4*)hrow;
            float ho[4] = {hv.x, hv.y, hv.z, hv.w};
            float hn[4];
            #pragma unroll
            for (int mi = 0; mi < 4; mi++){
                float r = sigm(ar[mi][ji] + br[ji]);
                float z = sigm(az[mi][ji] + bz[ji]);
                float n = tanh_f(anx[mi][ji] + bnx[ji] + r*(anh[mi][ji] + bnh[ji]));
                hn[mi] = n + z*(ho[mi] - n);          // (1-z)*n + z*h
            }
            *(float4*)hrow = make_float4(hn[0], hn[1], hn[2], hn[3]);
        }
        __syncthreads();

        // ---- y = h_new @ Wout^T + bout ; write output; y becomes next x ----
        {
            int i = tid & 31, mg = tid >> 5;          // warp-uniform mg -> broadcast LDS
            ull acc2[2];                               // pairs along m: {m0,m1},{m2,m3}
            acc2[0] = pk2(bo, bo);
            acc2[1] = pk2(bo, bo);
            #pragma unroll 8
            for (int k = 0; k < H_DIM; k++){
                float w = s_wout[k*I_DIM + i];
                ull wp = pk2(w, w);
                const ulonglong2 a =
                    *(const ulonglong2*)(s_state + (I_DIM+k)*SS + mg*4);
                ffma2(acc2[0], a.x, wp);
                ffma2(acc2[1], a.y, wp);
            }
            float acc[4];
            upk2(acc[0], acc[1], acc2[0]);
            upk2(acc[2], acc[3], acc2[1]);
            int mbase = m0 + mg*4;
            #pragma unroll
            for (int r2 = 0; r2 < 4; r2++)
                out[((mbase+r2)*STEPS + t)*I_DIM + i] = acc[r2];
            *(float4*)(s_state + i*SS + mg*4) =
                make_float4(acc[0], acc[1], acc[2], acc[3]);
        }
        __syncthreads();
    }
}

extern "C" void kernel_launch(void* const* d_in, const int* in_sizes, int n_in,
                              void* d_out, int out_size){
    const float* x    = (const float*)d_in[0];
    const float* h    = (const float*)d_in[1];
    const float* Wih  = (const float*)d_in[2];
    const float* Whh  = (const float*)d_in[3];
    const float* bih  = (const float*)d_in[4];
    const float* bhh  = (const float*)d_in[5];
    const float* Wout = (const float*)d_in[6];
    const float* bout = (const float*)d_in[7];
    float* out = (float*)d_out;

    prep_kernel<<<(K_TOT*N3 + 255)/256, 256>>>(Wih, Whh);

    cudaFuncSetAttribute(gru_kernel,
                         cudaFuncAttributeMaxDynamicSharedMemorySize, SMEM_BYTES);
    gru_kernel<<<BATCH/TM, NTHR, SMEM_BYTES>>>(x, h, bih, bhh, Wout, bout, out);
}

// round 11
// speedup vs baseline: 1.4342x; 1.4342x over previous
#include <cuda_runtime.h>
#include <cuda_fp16.h>
#include <cstdint>

#define T_IN 60
#define I_DIM 32
#define STEPS 30
#define TM 64
#define NTHR 512
#define KS 168            // state tile k-stride (halfs), conflict-free, >=160
#define WCH 40            // W chunk k-stride (halfs), 32 data + 8 pad
#define CHB 30720         // chunk bytes = 384*40*2
#define WOS 136           // Wout tile k-stride (halfs)

#define SM_BUF 0u         // 4 chunk slots  (122880 B)
#define SM_SHI 122880u    // state hi tile [64][168] half (21504)
#define SM_SLO 144384u    // state lo tile
#define SM_WOH 165888u    // Wout hi [32][136] half (8704)
#define SM_WOL 174592u
#define SM_BIA 183296u    // biases: 512 floats
#define SM_TOTAL 185344u

// W fused row = gate*128 + r (r,z,n), k: 0-127 = Whh cols, 128-159 = Wih cols.
// Stored as 5 k32-chunks, [row][40] layout (cols 32-39 pad).
__device__ __half g_W[2][5][384*WCH];

__global__ void prep_kernel(const float* __restrict__ Wih, const float* __restrict__ Whh){
    int idx = blockIdx.x*blockDim.x + threadIdx.x;
    if (idx >= 2*5*384*32) return;
    int img = idx / 61440, r1 = idx % 61440;
    int ch = r1 / 12288, r2 = r1 % 12288;
    int row = r2 >> 5, col = r2 & 31;
    int k = ch*32 + col;
    float w = (k < 128) ? Whh[row*128 + k] : Wih[row*32 + (k-128)];
    __half h = __float2half_rn(w);
    g_W[img][ch][row*WCH + col] = img ? __float2half_rn(w - __half2float(h)) : h;
}

__device__ __forceinline__ uint32_t su32(const void* p){
    uint32_t a; asm("{ .reg .u64 t; cvta.to.shared.u64 t, %1; cvt.u32.u64 %0, t; }":"=r"(a):"l"(p));
    return a;
}
__device__ __forceinline__ void cp16(uint32_t sd, const void* gs){
    asm volatile("cp.async.cg.shared.global [%0], [%1], 16;" :: "r"(sd), "l"(gs));
}
__device__ __forceinline__ void ldsm4(uint32_t* r, uint32_t a){
    asm volatile("ldmatrix.sync.aligned.m8n8.x4.shared.b16 {%0,%1,%2,%3}, [%4];"
        : "=r"(r[0]),"=r"(r[1]),"=r"(r[2]),"=r"(r[3]) : "r"(a));
}
__device__ __forceinline__ void mma(float* c, const uint32_t* a, uint32_t b0, uint32_t b1){
    asm volatile("mma.sync.aligned.m16n8k16.row.col.f32.f16.f16.f32 "
        "{%0,%1,%2,%3},{%4,%5,%6,%7},{%8,%9},{%0,%1,%2,%3};"
        : "+f"(c[0]),"+f"(c[1]),"+f"(c[2]),"+f"(c[3])
        : "r"(a[0]),"r"(a[1]),"r"(a[2]),"r"(a[3]),"r"(b0),"r"(b1));
}
__device__ __forceinline__ void issue_pair(uint32_t sb, int cnt, int tid){
    int pc = cnt % 5;
    uint32_t s0 = (uint32_t)((2*cnt)&3) * CHB;
    const char* h = (const char*)&g_W[0][pc][0];
    const char* l = (const char*)&g_W[1][pc][0];
    for (int o = tid; o < 1920; o += NTHR) cp16(sb + SM_BUF + s0 + o*16, h + o*16);
    asm volatile("cp.async.commit_group;");
    for (int o = tid; o < 1920; o += NTHR) cp16(sb + SM_BUF + s0 + CHB + o*16, l + o*16);
    asm volatile("cp.async.commit_group;");
}
__device__ __forceinline__ float sigm(float v){ return __fdividef(1.f, 1.f + __expf(-v)); }
__device__ __forceinline__ float tanh_f(float v){
    float e = __expf(-2.f*fabsf(v));
    float t = __fdividef(1.f - e, 1.f + e);
    return v < 0.f ? -t : t;
}
__device__ __forceinline__ void put_hl(unsigned char* sm, uint32_t off, float v){
    __half h = __float2half_rn(v);
    *(__half*)(sm + SM_SHI + off) = h;
    *(__half*)(sm + SM_SLO + off) = __float2half_rn(v - __half2float(h));
}

__global__ __launch_bounds__(NTHR,1)
void gru_kernel(const float* __restrict__ x, const float* __restrict__ h0,
                const float* __restrict__ bih, const float* __restrict__ bhh,
                const float* __restrict__ Wout, const float* __restrict__ bout,
                float* __restrict__ out){
    extern __shared__ unsigned char sm[];
    const uint32_t sb = su32(sm);
    const int tid = threadIdx.x, wid = tid>>5, lane = tid&31;
    const int m0 = blockIdx.x*TM;
    const int mt = wid&3, nt = wid>>2;

    // ---- init state tiles (hi/lo), Wout tiles, bias table ----
    for (int i = tid; i < TM*128; i += NTHR){
        int b = i>>7, k = i&127;
        put_hl(sm, (uint32_t)(b*KS + k)*2, h0[(m0+b)*128 + k]);
    }
    for (int i = tid; i < TM*I_DIM; i += NTHR){
        int b = i>>5, k = i&31;
        put_hl(sm, (uint32_t)(b*KS + 128 + k)*2, x[((m0+b)*T_IN + 30)*I_DIM + k]);
    }
    for (int i = tid; i < 32*128; i += NTHR){
        int r = i>>7, k = i&127;
        float v = Wout[i];
        __half h = __float2half_rn(v);
        *(__half*)(sm + SM_WOH + (uint32_t)(r*WOS + k)*2) = h;
        *(__half*)(sm + SM_WOL + (uint32_t)(r*WOS + k)*2) = __float2half_rn(v - __half2float(h));
    }
    if (tid < 128){
        float* bs = (float*)(sm + SM_BIA);
        bs[tid]       = bih[tid]     + bhh[tid];
        bs[128+tid]   = bih[128+tid] + bhh[128+tid];
        bs[256+tid]   = bih[256+tid];
        bs[384+tid]   = bhh[256+tid];
    }

    // per-thread epilogue coords + h registers: idx = mi*8+ni*4+e
    float hp[16];
    #pragma unroll
    for (int mi = 0; mi < 2; mi++)
    #pragma unroll
    for (int ni = 0; ni < 2; ni++)
    #pragma unroll
    for (int e = 0; e < 4; e++){
        int j = mt*32 + mi*16 + (lane>>2) + 8*(e>>1);
        int b = nt*16 + ni*8 + (lane&3)*2 + (e&1);
        hp[mi*8+ni*4+e] = h0[(m0+b)*128 + j];
    }

    // ldmatrix lane-address bases
    const uint32_t aoff = (uint32_t)((lane&15)*WCH + (lane>>4)*8)*2;            // A (W chunks)
    const uint32_t brow = (uint32_t)(nt*16 + ((lane>>4)<<3) + (lane&7));
    const uint32_t boffh = sb + SM_SHI + (brow*KS + ((lane>>3)&1)*8)*2;          // B (state)
    const uint32_t boffl = boffh + (SM_SLO - SM_SHI);
    // y-GEMM bases (warps 0-7)
    const int mt2 = wid&1, nt2 = (wid>>1)&3;
    const uint32_t ybrow = (uint32_t)(nt2*16 + ((lane>>4)<<3) + (lane&7));
    const uint32_t ybh = sb + SM_SHI + (ybrow*KS + ((lane>>3)&1)*8)*2;
    const uint32_t ybl = ybh + (SM_SLO - SM_SHI);
    const uint32_t yao = (uint32_t)((mt2*16 + (lane&15))*WOS + (lane>>4)*8)*2;
    float bo[2];
    if (wid < 8){
        bo[0] = bout[mt2*16 + (lane>>2)];
        bo[1] = bout[mt2*16 + (lane>>2) + 8];
    }

    issue_pair(sb, 0, tid); issue_pair(sb, 1, tid);

    int cnt = 0;
    for (int t = 0; t < STEPS; t++){
        float acc[4][2][2][4] = {};   // [r,z,nh,nx][mi][ni][e]
        #pragma unroll
        for (int p = 0; p < 5; p++){
            asm volatile("cp.async.wait_group 2;" ::: "memory");
            __syncthreads();                       // chunk pair visible; old readers done
            uint32_t hib = sb + SM_BUF + (uint32_t)((2*cnt)&3)*CHB;
            uint32_t lob = hib + CHB;
            #pragma unroll
            for (int kk = 0; kk < 2; kk++){
                uint32_t bcol = (uint32_t)(p*32 + kk*16)*2;
                uint32_t bh[4], bl[4];
                ldsm4(bh, boffh + bcol);
                ldsm4(bl, boffl + bcol);
                #pragma unroll
                for (int g = 0; g < 3; g++){
                    const int gi = (g < 2) ? g : ((p == 4) ? 3 : 2);
                    uint32_t ro = (uint32_t)((g*128 + mt*32)*WCH + kk*16)*2;
                    uint32_t ah0[4], ah1[4], al0[4], al1[4];
                    ldsm4(ah0, hib + aoff + ro);
                    ldsm4(ah1, hib + aoff + ro + 16*WCH*2);
                    mma(acc[gi][0][0], ah0, bh[0], bh[1]);
                    mma(acc[gi][0][1], ah0, bh[2], bh[3]);
                    mma(acc[gi][1][0], ah1, bh[0], bh[1]);
                    mma(acc[gi][1][1], ah1, bh[2], bh[3]);
                    mma(acc[gi][0][0], ah0, bl[0], bl[1]);
                    mma(acc[gi][0][1], ah0, bl[2], bl[3]);
                    mma(acc[gi][1][0], ah1, bl[0], bl[1]);
                    mma(acc[gi][1][1], ah1, bl[2], bl[3]);
                    ldsm4(al0, lob + aoff + ro);
                    ldsm4(al1, lob + aoff + ro + 16*WCH*2);
                    mma(acc[gi][0][0], al0, bh[0], bh[1]);
                    mma(acc[gi][0][1], al0, bh[2], bh[3]);
                    mma(acc[gi][1][0], al1, bh[0], bh[1]);
                    mma(acc[gi][1][1], al1, bh[2], bh[3]);
                }
            }
            __syncthreads();                       // all reads of this pair done
            issue_pair(sb, cnt + 2, tid);          // overwrite this pair's slots
            cnt++;
        }

        // ---- gates + h update; write h-part of state tiles ----
        const float* bs = (const float*)(sm + SM_BIA);
        #pragma unroll
        for (int mi = 0; mi < 2; mi++)
        #pragma unroll
        for (int ni = 0; ni < 2; ni++)
        #pragma unroll
        for (int e = 0; e < 4; e++){
            int j = mt*32 + mi*16 + (lane>>2) + 8*(e>>1);
            int b = nt*16 + ni*8 + (lane&3)*2 + (e&1);
            int ix = mi*8 + ni*4 + e;
            float r = sigm(acc[0][mi][ni][e] + bs[j]);
            float z = sigm(acc[1][mi][ni][e] + bs[128+j]);
            float n = tanh_f(acc[3][mi][ni][e] + bs[256+j] + r*(acc[2][mi][ni][e] + bs[384+j]));
            float h = n + z*(hp[ix] - n);
            hp[ix] = h;
            put_hl(sm, (uint32_t)(b*KS + j)*2, h);
        }
        __syncthreads();                           // new h visible

        // ---- y = Wout @ h + bout (warps 0-7), feed back into x slice ----
        if (wid < 8){
            float cy[2][4] = {};
            #pragma unroll
            for (int ks = 0; ks < 8; ks++){
                uint32_t bcol = (uint32_t)(ks*16)*2;
                uint32_t bh[4], bl[4], ah[4], al[4];
                ldsm4(bh, ybh + bcol);
                ldsm4(bl, ybl + bcol);
                ldsm4(ah, sb + SM_WOH + yao + bcol);
                mma(cy[0], ah, bh[0], bh[1]);
                mma(cy[1], ah, bh[2], bh[3]);
                mma(cy[0], ah, bl[0], bl[1]);
                mma(cy[1], ah, bl[2], bl[3]);
                ldsm4(al, sb + SM_WOL + yao + bcol);
                mma(cy[0], al, bh[0], bh[1]);
                mma(cy[1], al, bh[2], bh[3]);
            }
            #pragma unroll
            for (int ni = 0; ni < 2; ni++)
            #pragma unroll
            for (int e = 0; e < 4; e++){
                int i = mt2*16 + (lane>>2) + 8*(e>>1);
                int b = nt2*16 + ni*8 + (lane&3)*2 + (e&1);
                float y = cy[ni][e] + bo[e>>1];
                out[((m0+b)*STEPS + t)*I_DIM + i] = y;
                put_hl(sm, (uint32_t)(b*KS + 128 + i)*2, y);
            }
        }
        __syncthreads();                           // new x visible; y reads done
    }
}

extern "C" void kernel_launch(void* const* d_in, const int* in_sizes, int n_in,
                              void* d_out, int out_size){
    const float* x    = (const float*)d_in[0];
    const float* h    = (const float*)d_in[1];
    const float* Wih  = (const float*)d_in[2];
    const float* Whh  = (const float*)d_in[3];
    const float* bih  = (const float*)d_in[4];
    const float* bhh  = (const float*)d_in[5];
    const float* Wout = (const float*)d_in[6];
    const float* bout = (const float*)d_in[7];
    float* out = (float*)d_out;

    prep_kernel<<<(2*5*384*32 + 255)/256, 256>>>(Wih, Whh);

    cudaFuncSetAttribute(gru_kernel,
                         cudaFuncAttributeMaxDynamicSharedMemorySize, SM_TOTAL);
    gru_kernel<<<16384/TM, NTHR, SM_TOTAL>>>(x, h, bih, bhh, Wout, bout, out);
}

// round 13
// speedup vs baseline: 2.0091x; 1.4009x over previous
#include <cuda_runtime.h>
#include <cuda_fp16.h>
#include <cstdint>

#define T_IN 60
#define STEPS 30
#define TM 64
#define NTHR 512
#define WS 136               // row stride (halfs) for W image and state tiles

#define SM_W    0u           // 576*136*2 = 156672
#define SM_SHI  156672u      // state hi [64][136] half
#define SM_SLO  174080u      // state lo
#define SM_BIA  191488u      // 512 floats
#define SM_TOTAL 193536u

// Weight image rows: [0,128) r = Whh_r + Wih_r*Wout ; [128,256) z merged;
// [256,384) nh = Whh_n ; [384,512) nx = Wih_n*Wout ; [512,544) Wout hi ; [544,576) Wout lo
__device__ __half g_Wimg[576*WS];
__device__ float  g_bias[512];           // [0,256) r/z const; [256,384) cnx; [384,512) cnh
__device__ float  g_corr[16384*384];     // step-0 correction

__global__ void prep1(const float* Wih, const float* Whh, const float* Wout,
                      const float* bih, const float* bhh, const float* bout){
    int idx = blockIdx.x*blockDim.x + threadIdx.x;
    if (idx < 576*128){
        int row = idx >> 7, k = idx & 127;
        float v;
        if (row < 256){
            float d = 0.f;
            for (int i = 0; i < 32; i++) d += Wih[row*32+i]*Wout[i*128+k];
            v = Whh[row*128+k] + d;
        } else if (row < 384){
            v = Whh[row*128+k];
        } else if (row < 512){
            int j = row - 128;                  // Wih gate-n row 256..383
            float d = 0.f;
            for (int i = 0; i < 32; i++) d += Wih[j*32+i]*Wout[i*128+k];
            v = d;
        } else {
            v = Wout[(row&31)*128 + k];
        }
        __half h = __float2half_rn(v);
        if (row >= 544) h = __float2half_rn(v - __half2float(__float2half_rn(v)));
        g_Wimg[row*WS + k] = h;
    } else if (idx < 576*128 + 384){
        int j = idx - 576*128;
        float bb = 0.f;
        for (int i = 0; i < 32; i++) bb += Wih[j*32+i]*bout[i];
        if (j < 256) g_bias[j] = bih[j] + bhh[j] + bb;
        else { g_bias[j] = bih[j] + bb; g_bias[j+128] = bhh[j]; }
    }
}

// corr[b][j] = Wih_j . (x0[b] - Wout*h0[b] - bout)
__global__ __launch_bounds__(256,1) void prep2(const float* x, const float* h0,
        const float* Wih, const float* Wout, const float* bout){
    extern __shared__ float s[];            // Wout 4096 | Wih 12288 | u 2048
    float* sWo = s; float* sWi = s + 4096; float* su = s + 16384;
    int tid = threadIdx.x; int m0 = blockIdx.x*TM;
    for (int i = tid; i < 4096;  i += 256) sWo[i] = Wout[i];
    for (int i = tid; i < 12288; i += 256) sWi[i] = Wih[i];
    __syncthreads();
    for (int q = tid; q < TM*32; q += 256){
        int b = q >> 5, i = q & 31;
        float a = x[((m0+b)*T_IN + 30)*32 + i] - bout[i];
        const float* hp = h0 + (m0+b)*128;
        for (int k = 0; k < 128; k++) a -= sWo[i*128+k]*hp[k];
        su[q] = a;
    }
    __syncthreads();
    for (int q = tid; q < TM*384; q += 256){
        int b = q / 384, j = q - b*384;
        float a = 0.f;
        const float* up = su + b*32;
        for (int i = 0; i < 32; i++) a += sWi[j*32+i]*up[i];
        g_corr[(m0+b)*384 + j] = a;
    }
}

__device__ __forceinline__ uint32_t su32(const void* p){
    uint32_t a; asm("{ .reg .u64 t; cvta.to.shared.u64 t, %1; cvt.u32.u64 %0, t; }":"=r"(a):"l"(p));
    return a;
}
__device__ __forceinline__ void cp16(uint32_t sd, const void* gs){
    asm volatile("cp.async.cg.shared.global [%0], [%1], 16;" :: "r"(sd), "l"(gs));
}
__device__ __forceinline__ void ldsm4(uint32_t* r, uint32_t a){
    asm volatile("ldmatrix.sync.aligned.m8n8.x4.shared.b16 {%0,%1,%2,%3}, [%4];"
        : "=r"(r[0]),"=r"(r[1]),"=r"(r[2]),"=r"(r[3]) : "r"(a));
}
__device__ __forceinline__ void mma(float* c, const uint32_t* a, uint32_t b0, uint32_t b1){
    asm volatile("mma.sync.aligned.m16n8k16.row.col.f32.f16.f16.f32 "
        "{%0,%1,%2,%3},{%4,%5,%6,%7},{%8,%9},{%0,%1,%2,%3};"
        : "+f"(c[0]),"+f"(c[1]),"+f"(c[2]),"+f"(c[3])
        : "r"(a[0]),"r"(a[1]),"r"(a[2]),"r"(a[3]),"r"(b0),"r"(b1));
}
__device__ __forceinline__ float sigm(float v){ return __fdividef(1.f, 1.f + __expf(-v)); }
__device__ __forceinline__ float tanh_f(float v){
    float e = __expf(-2.f*fabsf(v));
    float t = __fdividef(1.f - e, 1.f + e);
    return v < 0.f ? -t : t;
}
__device__ __forceinline__ void put_hl(unsigned char* sm, uint32_t off, float v){
    __half h = __float2half_rn(v);
    *(__half*)(sm + SM_SHI + off) = h;
    *(__half*)(sm + SM_SLO + off) = __float2half_rn(v - __half2float(h));
}

__global__ __launch_bounds__(NTHR,1)
void gru_kernel(const float* __restrict__ h0, const float* __restrict__ boutp,
                float* __restrict__ out){
    extern __shared__ unsigned char sm[];
    const uint32_t sb = su32(sm);
    const int tid = threadIdx.x, wid = tid>>5, lane = tid&31;
    const int m0 = blockIdx.x*TM;
    const int mt = wid&3, nt = wid>>2;
    const bool isy = (mt == nt);     // one y-warp per SMSP

    // resident weight image + biases
    for (int o = tid*16; o < 156672; o += NTHR*16)
        cp16(sb + SM_W + o, (const char*)g_Wimg + o);
    asm volatile("cp.async.commit_group;");
    for (int i = tid; i < 512; i += NTHR)
        ((float*)(sm + SM_BIA))[i] = g_bias[i];

    // state tiles
    for (int q = tid; q < TM*128; q += NTHR){
        int b = q >> 7, k = q & 127;
        put_hl(sm, (uint32_t)(b*WS + k)*2, h0[(m0+b)*128 + k]);
    }

    float bo[4];
    if (isy){
        #pragma unroll
        for (int q = 0; q < 4; q++) bo[q] = __ldg(boutp + (lane>>2) + q*8);
    }

    // ldmatrix bases
    const uint32_t bB = sb + SM_SHI +
        ((uint32_t)(nt*16 + ((lane>>4)<<3) + (lane&7))*WS + ((lane>>3)&1)*8)*2;
    const uint32_t aG = sb + SM_W +
        ((uint32_t)((mt*32 + (lane&15))*WS) + (lane>>4)*8)*2;
    const uint32_t aY = sb + SM_W +
        ((uint32_t)((512 + (lane&15))*WS) + (lane>>4)*8)*2;

    asm volatile("cp.async.wait_all;" ::: "memory");
    __syncthreads();

    for (int t = 0; t < STEPS; t++){
        float acc[4][2][2][4] = {};
        float yac[2][2][4] = {};
        #pragma unroll
        for (int kk = 0; kk < 8; kk++){
            const uint32_t ko = (uint32_t)kk*32;
            uint32_t bh[4], bl[4];
            ldsm4(bh, bB + ko);
            ldsm4(bl, bB + 17408u + ko);
            #pragma unroll
            for (int g = 0; g < 4; g++){
                uint32_t a0[4], a1[4];
                ldsm4(a0, aG + g*34816u + ko);
                ldsm4(a1, aG + g*34816u + 4352u + ko);
                mma(acc[g][0][0], a0, bh[0], bh[1]);
                mma(acc[g][0][1], a0, bh[2], bh[3]);
                mma(acc[g][1][0], a1, bh[0], bh[1]);
                mma(acc[g][1][1], a1, bh[2], bh[3]);
                mma(acc[g][0][0], a0, bl[0], bl[1]);
                mma(acc[g][0][1], a0, bl[2], bl[3]);
                mma(acc[g][1][0], a1, bl[0], bl[1]);
                mma(acc[g][1][1], a1, bl[2], bl[3]);
            }
            if (isy){
                uint32_t yh0[4], yh1[4], yl0[4], yl1[4];
                ldsm4(yh0, aY + ko);
                ldsm4(yh1, aY + 4352u + ko);
                ldsm4(yl0, aY + 8704u + ko);
                ldsm4(yl1, aY + 8704u + 4352u + ko);
                mma(yac[0][0], yh0, bh[0], bh[1]); mma(yac[0][1], yh0, bh[2], bh[3]);
                mma(yac[1][0], yh1, bh[0], bh[1]); mma(yac[1][1], yh1, bh[2], bh[3]);
                mma(yac[0][0], yh0, bl[0], bl[1]); mma(yac[0][1], yh0, bl[2], bl[3]);
                mma(yac[1][0], yh1, bl[0], bl[1]); mma(yac[1][1], yh1, bl[2], bl[3]);
                mma(yac[0][0], yl0, bh[0], bh[1]); mma(yac[0][1], yl0, bh[2], bh[3]);
                mma(yac[1][0], yl1, bh[0], bh[1]); mma(yac[1][1], yl1, bh[2], bh[3]);
            }
        }

        // all warps done READING the state tiles before anyone writes h_new
        __syncthreads();

        // epilogue: gates + h update (writes state), y output for t-1
        const float* gb = (const float*)(sm + SM_BIA);
        #pragma unroll
        for (int mi = 0; mi < 2; mi++)
        #pragma unroll
        for (int ni = 0; ni < 2; ni++)
        #pragma unroll
        for (int e = 0; e < 4; e++){
            int j = mt*32 + (lane>>2) + (mi*2 + (e>>1))*8;
            int b = nt*16 + ni*8 + (lane&3)*2 + (e&1);
            float ar = acc[0][mi][ni][e], az = acc[1][mi][ni][e];
            float ah = acc[2][mi][ni][e], ax = acc[3][mi][ni][e];
            if (t == 0){
                const float* cp = g_corr + (m0+b)*384 + j;
                ar += cp[0]; az += cp[128]; ax += cp[256];
            }
            uint32_t so = (uint32_t)(b*WS + j)*2;
            float hv = __half2float(*(__half*)(sm+SM_SHI+so))
                     + __half2float(*(__half*)(sm+SM_SLO+so));
            float r = sigm(ar + gb[j]);
            float z = sigm(az + gb[128+j]);
            float n = tanh_f(ax + gb[256+j] + r*(ah + gb[384+j]));
            put_hl(sm, so, n + z*(hv - n));
        }
        if (isy && t > 0){
            #pragma unroll
            for (int mi = 0; mi < 2; mi++)
            #pragma unroll
            for (int ni = 0; ni < 2; ni++)
            #pragma unroll
            for (int e = 0; e < 4; e++){
                int i = (lane>>2) + (mi*2 + (e>>1))*8;
                int b = nt*16 + ni*8 + (lane&3)*2 + (e&1);
                out[((m0+b)*STEPS + (t-1))*32 + i] = yac[mi][ni][e] + bo[mi*2 + (e>>1)];
            }
        }
        __syncthreads();
    }

    // final y_29 = Wout * h_29
    if (isy){
        float yac[2][2][4] = {};
        #pragma unroll
        for (int kk = 0; kk < 8; kk++){
            const uint32_t ko = (uint32_t)kk*32;
            uint32_t bh[4], bl[4], yh0[4], yh1[4], yl0[4], yl1[4];
            ldsm4(bh, bB + ko);
            ldsm4(bl, bB + 17408u + ko);
            ldsm4(yh0, aY + ko);
            ldsm4(yh1, aY + 4352u + ko);
            ldsm4(yl0, aY + 8704u + ko);
            ldsm4(yl1, aY + 8704u + 4352u + ko);
            mma(yac[0][0], yh0, bh[0], bh[1]); mma(yac[0][1], yh0, bh[2], bh[3]);
            mma(yac[1][0], yh1, bh[0], bh[1]); mma(yac[1][1], yh1, bh[2], bh[3]);
            mma(yac[0][0], yh0, bl[0], bl[1]); mma(yac[0][1], yh0, bl[2], bl[3]);
            mma(yac[1][0], yh1, bl[0], bl[1]); mma(yac[1][1], yh1, bl[2], bl[3]);
            mma(yac[0][0], yl0, bh[0], bh[1]); mma(yac[0][1], yl0, bh[2], bh[3]);
            mma(yac[1][0], yl1, bh[0], bh[1]); mma(yac[1][1], yl1, bh[2], bh[3]);
        }
        #pragma unroll
        for (int mi = 0; mi < 2; mi++)
        #pragma unroll
        for (int ni = 0; ni < 2; ni++)
        #pragma unroll
        for (int e = 0; e < 4; e++){
            int i = (lane>>2) + (mi*2 + (e>>1))*8;
            int b = nt*16 + ni*8 + (lane&3)*2 + (e&1);
            out[((m0+b)*STEPS + 29)*32 + i] = yac[mi][ni][e] + bo[mi*2 + (e>>1)];
        }
    }
}

extern "C" void kernel_launch(void* const* d_in, const int* in_sizes, int n_in,
                              void* d_out, int out_size){
    const float* x    = (const float*)d_in[0];
    const float* h    = (const float*)d_in[1];
    const float* Wih  = (const float*)d_in[2];
    const float* Whh  = (const float*)d_in[3];
    const float* bih  = (const float*)d_in[4];
    const float* bhh  = (const float*)d_in[5];
    const float* Wout = (const float*)d_in[6];
    const float* bout = (const float*)d_in[7];
    float* out = (float*)d_out;

    prep1<<<(576*128 + 384 + 255)/256, 256>>>(Wih, Whh, Wout, bih, bhh, bout);

    cudaFuncSetAttribute(prep2, cudaFuncAttributeMaxDynamicSharedMemorySize, 73728);
    prep2<<<16384/TM, 256, 73728>>>(x, h, Wih, Wout, bout);

    cudaFuncSetAttribute(gru_kernel,
                         cudaFuncAttributeMaxDynamicSharedMemorySize, SM_TOTAL);
    gru_kernel<<<16384/TM, NTHR, SM_TOTAL>>>(h, bout, out);
}

// round 15
// speedup vs baseline: 2.1569x; 1.0735x over previous
#include <cuda_runtime.h>
#include <cuda_fp16.h>
#include <cstdint>

#define T_IN 60
#define STEPS 30
#define TM 64
#define NTHR 512
#define WS 136               // weight image row stride (halfs)
#define BS2 72               // state tile row stride (halfs), k-major, conflict-free

#define SM_W    0u           // 576*136*2 = 156672
#define SM_SHI  156672u      // state hi [128][72] half = 18432
#define SM_SLO  175104u      // state lo
#define SM_BIA  193536u      // 512 floats
#define SM_TOTAL 195584u

// Weight image rows: [0,128) r = Whh_r + Wih_r*Wout ; [128,256) z merged;
// [256,384) nh = Whh_n ; [384,512) nx = Wih_n*Wout ; [512,544) Wout hi ; [544,576) Wout lo
__device__ __half g_Wimg[576*WS];
__device__ float  g_bias[512];
__device__ float  g_corr[16384*384];     // step-0 correction

__global__ void prep1(const float* Wih, const float* Whh, const float* Wout,
                      const float* bih, const float* bhh, const float* bout){
    int idx = blockIdx.x*blockDim.x + threadIdx.x;
    if (idx < 576*128){
        int row = idx >> 7, k = idx & 127;
        float v;
        if (row < 256){
            float d = 0.f;
            for (int i = 0; i < 32; i++) d += Wih[row*32+i]*Wout[i*128+k];
            v = Whh[row*128+k] + d;
        } else if (row < 384){
            v = Whh[row*128+k];
        } else if (row < 512){
            int j = row - 128;
            float d = 0.f;
            for (int i = 0; i < 32; i++) d += Wih[j*32+i]*Wout[i*128+k];
            v = d;
        } else {
            v = Wout[(row&31)*128 + k];
        }
        __half h = __float2half_rn(v);
        if (row >= 544) h = __float2half_rn(v - __half2float(__float2half_rn(v)));
        g_Wimg[row*WS + k] = h;
    } else if (idx < 576*128 + 384){
        int j = idx - 576*128;
        float bb = 0.f;
        for (int i = 0; i < 32; i++) bb += Wih[j*32+i]*bout[i];
        if (j < 256) g_bias[j] = bih[j] + bhh[j] + bb;
        else { g_bias[j] = bih[j] + bb; g_bias[j+128] = bhh[j]; }
    }
}

// corr[b][j] = Wih_j . (x0[b] - Wout*h0[b] - bout)
__global__ __launch_bounds__(256,1) void prep2(const float* x, const float* h0,
        const float* Wih, const float* Wout, const float* bout){
    extern __shared__ float s[];
    float* sWo = s; float* sWi = s + 4096; float* su = s + 16384;
    int tid = threadIdx.x; int m0 = blockIdx.x*TM;
    for (int i = tid; i < 4096;  i += 256) sWo[i] = Wout[i];
    for (int i = tid; i < 12288; i += 256) sWi[i] = Wih[i];
    __syncthreads();
    for (int q = tid; q < TM*32; q += 256){
        int b = q >> 5, i = q & 31;
        float a = x[((m0+b)*T_IN + 30)*32 + i] - bout[i];
        const float* hp = h0 + (m0+b)*128;
        for (int k = 0; k < 128; k++) a -= sWo[i*128+k]*hp[k];
        su[q] = a;
    }
    __syncthreads();
    for (int q = tid; q < TM*384; q += 256){
        int b = q / 384, j = q - b*384;
        float a = 0.f;
        const float* up = su + b*32;
        for (int i = 0; i < 32; i++) a += sWi[j*32+i]*up[i];
        g_corr[(m0+b)*384 + j] = a;
    }
}

__device__ __forceinline__ uint32_t su32(const void* p){
    uint32_t a; asm("{ .reg .u64 t; cvta.to.shared.u64 t, %1; cvt.u32.u64 %0, t; }":"=r"(a):"l"(p));
    return a;
}
__device__ __forceinline__ void cp16(uint32_t sd, const void* gs){
    asm volatile("cp.async.cg.shared.global [%0], [%1], 16;" :: "r"(sd), "l"(gs));
}
__device__ __forceinline__ void ldsm4(uint32_t* r, uint32_t a){
    asm volatile("ldmatrix.sync.aligned.m8n8.x4.shared.b16 {%0,%1,%2,%3}, [%4];"
        : "=r"(r[0]),"=r"(r[1]),"=r"(r[2]),"=r"(r[3]) : "r"(a));
}
__device__ __forceinline__ void ldsm4t(uint32_t* r, uint32_t a){
    asm volatile("ldmatrix.sync.aligned.m8n8.x4.trans.shared.b16 {%0,%1,%2,%3}, [%4];"
        : "=r"(r[0]),"=r"(r[1]),"=r"(r[2]),"=r"(r[3]) : "r"(a));
}
__device__ __forceinline__ void mma(float* c, const uint32_t* a, uint32_t b0, uint32_t b1){
    asm volatile("mma.sync.aligned.m16n8k16.row.col.f32.f16.f16.f32 "
        "{%0,%1,%2,%3},{%4,%5,%6,%7},{%8,%9},{%0,%1,%2,%3};"
        : "+f"(c[0]),"+f"(c[1]),"+f"(c[2]),"+f"(c[3])
        : "r"(a[0]),"r"(a[1]),"r"(a[2]),"r"(a[3]),"r"(b0),"r"(b1));
}
__device__ __forceinline__ float sigm(float v){ return __fdividef(1.f, 1.f + __expf(-v)); }
__device__ __forceinline__ float tanh_f(float v){
    float e = __expf(-2.f*fabsf(v));
    float t = __fdividef(1.f - e, 1.f + e);
    return v < 0.f ? -t : t;
}
__device__ __forceinline__ void put_hl(unsigned char* sm, uint32_t off, float v){
    __half h = __float2half_rn(v);
    *(__half*)(sm + SM_SHI + off) = h;
    *(__half*)(sm + SM_SLO + off) = __float2half_rn(v - __half2float(h));
}

__global__ __launch_bounds__(NTHR,1)
void gru_kernel(const float* __restrict__ h0, const float* __restrict__ boutp,
                float* __restrict__ out){
    extern __shared__ unsigned char sm[];
    const uint32_t sb = su32(sm);
    const int tid = threadIdx.x, wid = tid>>5, lane = tid&31;
    const int m0 = blockIdx.x*TM;
    const int mt = wid&3, nt = wid>>2;
    const bool isy = (mt == nt);     // one y-warp per SMSP

    // resident weight image + biases
    for (int o = tid*16; o < 156672; o += NTHR*16)
        cp16(sb + SM_W + o, (const char*)g_Wimg + o);
    asm volatile("cp.async.commit_group;");
    for (int i = tid; i < 512; i += NTHR)
        ((float*)(sm + SM_BIA))[i] = g_bias[i];

    // state tiles, k-major [k][b]
    for (int q = tid; q < TM*128; q += NTHR){
        int b = q >> 7, k = q & 127;
        put_hl(sm, (uint32_t)(k*BS2 + b)*2, h0[(m0+b)*128 + k]);
    }

    float bo[4];
    if (isy){
        #pragma unroll
        for (int q = 0; q < 4; q++) bo[q] = __ldg(boutp + (lane>>2) + q*8);
    }

    // ldmatrix bases
    const uint32_t bB = sb + SM_SHI +
        ((uint32_t)((lane&7) + ((lane>>3)&1)*8)*BS2 + (uint32_t)(nt*16 + (lane>>4)*8))*2;
    const uint32_t aG = sb + SM_W +
        ((uint32_t)((mt*32 + (lane&15))*WS) + (lane>>4)*8)*2;
    const uint32_t aY = sb + SM_W +
        ((uint32_t)((512 + (lane&15))*WS) + (lane>>4)*8)*2;

    asm volatile("cp.async.wait_all;" ::: "memory");
    __syncthreads();

    for (int t = 0; t < STEPS; t++){
        float acc[4][2][2][4] = {};
        float yac[2][2][4] = {};
        #pragma unroll
        for (int kk = 0; kk < 8; kk++){
            const uint32_t bko = (uint32_t)kk*16*BS2*2;   // advance 16 k-rows
            const uint32_t ako = (uint32_t)kk*32;
            uint32_t bh[4], bl[4];
            ldsm4t(bh, bB + bko);
            ldsm4t(bl, bB + 18432u + bko);
            #pragma unroll
            for (int g = 0; g < 4; g++){
                uint32_t a0[4], a1[4];
                ldsm4(a0, aG + g*34816u + ako);
                ldsm4(a1, aG + g*34816u + 4352u + ako);
                mma(acc[g][0][0], a0, bh[0], bh[1]);
                mma(acc[g][0][1], a0, bh[2], bh[3]);
                mma(acc[g][1][0], a1, bh[0], bh[1]);
                mma(acc[g][1][1], a1, bh[2], bh[3]);
                mma(acc[g][0][0], a0, bl[0], bl[1]);
                mma(acc[g][0][1], a0, bl[2], bl[3]);
                mma(acc[g][1][0], a1, bl[0], bl[1]);
                mma(acc[g][1][1], a1, bl[2], bl[3]);
            }
            if (isy){
                uint32_t yh0[4], yh1[4], yl0[4], yl1[4];
                ldsm4(yh0, aY + ako);
                ldsm4(yh1, aY + 4352u + ako);
                ldsm4(yl0, aY + 8704u + ako);
                ldsm4(yl1, aY + 8704u + 4352u + ako);
                mma(yac[0][0], yh0, bh[0], bh[1]); mma(yac[0][1], yh0, bh[2], bh[3]);
                mma(yac[1][0], yh1, bh[0], bh[1]); mma(yac[1][1], yh1, bh[2], bh[3]);
                mma(yac[0][0], yh0, bl[0], bl[1]); mma(yac[0][1], yh0, bl[2], bl[3]);
                mma(yac[1][0], yh1, bl[0], bl[1]); mma(yac[1][1], yh1, bl[2], bl[3]);
                mma(yac[0][0], yl0, bh[0], bh[1]); mma(yac[0][1], yl0, bh[2], bh[3]);
                mma(yac[1][0], yl1, bh[0], bh[1]); mma(yac[1][1], yl1, bh[2], bh[3]);
            }
        }

        // all warps done READING state before anyone writes h_new
        __syncthreads();

        const float* gb = (const float*)(sm + SM_BIA);
        #pragma unroll
        for (int mi = 0; mi < 2; mi++)
        #pragma unroll
        for (int ni = 0; ni < 2; ni++)
        #pragma unroll
        for (int ep = 0; ep < 2; ep++){
            int j = mt*32 + (lane>>2) + (mi*2 + ep)*8;
            int b = nt*16 + ni*8 + (lane&3)*2;
            float ar0 = acc[0][mi][ni][ep*2],   ar1 = acc[0][mi][ni][ep*2+1];
            float az0 = acc[1][mi][ni][ep*2],   az1 = acc[1][mi][ni][ep*2+1];
            float ah0 = acc[2][mi][ni][ep*2],   ah1 = acc[2][mi][ni][ep*2+1];
            float ax0 = acc[3][mi][ni][ep*2],   ax1 = acc[3][mi][ni][ep*2+1];
            if (t == 0){
                const float* c0 = g_corr + (m0+b)*384 + j;
                const float* c1 = c0 + 384;
                ar0 += c0[0]; az0 += c0[128]; ax0 += c0[256];
                ar1 += c1[0]; az1 += c1[128]; ax1 += c1[256];
            }
            uint32_t so = (uint32_t)(j*BS2 + b)*2;
            __half2 hh = *(__half2*)(sm + SM_SHI + so);
            __half2 hl = *(__half2*)(sm + SM_SLO + so);
            float hv0 = __low2float(hh)  + __low2float(hl);
            float hv1 = __high2float(hh) + __high2float(hl);
            float bj_r = gb[j], bj_z = gb[128+j], bj_x = gb[256+j], bj_h = gb[384+j];
            float r0 = sigm(ar0 + bj_r), r1 = sigm(ar1 + bj_r);
            float z0 = sigm(az0 + bj_z), z1 = sigm(az1 + bj_z);
            float n0 = tanh_f(ax0 + bj_x + r0*(ah0 + bj_h));
            float n1 = tanh_f(ax1 + bj_x + r1*(ah1 + bj_h));
            float o0 = n0 + z0*(hv0 - n0);
            float o1 = n1 + z1*(hv1 - n1);
            __half p0 = __float2half_rn(o0), p1 = __float2half_rn(o1);
            *(__half2*)(sm + SM_SHI + so) = __halves2half2(p0, p1);
            *(__half2*)(sm + SM_SLO + so) = __halves2half2(
                __float2half_rn(o0 - __half2float(p0)),
                __float2half_rn(o1 - __half2float(p1)));
        }
        if (isy && t > 0){
            #pragma unroll
            for (int mi = 0; mi < 2; mi++)
            #pragma unroll
            for (int ni = 0; ni < 2; ni++)
            #pragma unroll
            for (int e = 0; e < 4; e++){
                int i = (lane>>2) + (mi*2 + (e>>1))*8;
                int b = nt*16 + ni*8 + (lane&3)*2 + (e&1);
                out[((m0+b)*STEPS + (t-1))*32 + i] = yac[mi][ni][e] + bo[mi*2 + (e>>1)];
            }
        }
        __syncthreads();
    }

    // final y_29 = Wout * h_29
    if (isy){
        float yac[2][2][4] = {};
        #pragma unroll
        for (int kk = 0; kk < 8; kk++){
            const uint32_t bko = (uint32_t)kk*16*BS2*2;
            const uint32_t ako = (uint32_t)kk*32;
            uint32_t bh[4], bl[4], yh0[4], yh1[4], yl0[4], yl1[4];
            ldsm4t(bh, bB + bko);
            ldsm4t(bl, bB + 18432u + bko);
            ldsm4(yh0, aY + ako);
            ldsm4(yh1, aY + 4352u + ako);
            ldsm4(yl0, aY + 8704u + ako);
            ldsm4(yl1, aY + 8704u + 4352u + ako);
            mma(yac[0][0], yh0, bh[0], bh[1]); mma(yac[0][1], yh0, bh[2], bh[3]);
            mma(yac[1][0], yh1, bh[0], bh[1]); mma(yac[1][1], yh1, bh[2], bh[3]);
            mma(yac[0][0], yh0, bl[0], bl[1]); mma(yac[0][1], yh0, bl[2], bl[3]);
            mma(yac[1][0], yh1, bl[0], bl[1]); mma(yac[1][1], yh1, bl[2], bl[3]);
            mma(yac[0][0], yl0, bh[0], bh[1]); mma(yac[0][1], yl0, bh[2], bh[3]);
            mma(yac[1][0], yl1, bh[0], bh[1]); mma(yac[1][1], yl1, bh[2], bh[3]);
        }
        #pragma unroll
        for (int mi = 0; mi < 2; mi++)
        #pragma unroll
        for (int ni = 0; ni < 2; ni++)
        #pragma unroll
        for (int e = 0; e < 4; e++){
            int i = (lane>>2) + (mi*2 + (e>>1))*8;
            int b = nt*16 + ni*8 + (lane&3)*2 + (e&1);
            out[((m0+b)*STEPS + 29)*32 + i] = yac[mi][ni][e] + bo[mi*2 + (e>>1)];
        }
    }
}

extern "C" void kernel_launch(void* const* d_in, const int* in_sizes, int n_in,
                              void* d_out, int out_size){
    const float* x    = (const float*)d_in[0];
    const float* h    = (const float*)d_in[1];
    const float* Wih  = (const float*)d_in[2];
    const float* Whh  = (const float*)d_in[3];
    const float* bih  = (const float*)d_in[4];
    const float* bhh  = (const float*)d_in[5];
    const float* Wout = (const float*)d_in[6];
    const float* bout = (const float*)d_in[7];
    float* out = (float*)d_out;

    prep1<<<(576*128 + 384 + 255)/256, 256>>>(Wih, Whh, Wout, bih, bhh, bout);

    cudaFuncSetAttribute(prep2, cudaFuncAttributeMaxDynamicSharedMemorySize, 73728);
    prep2<<<16384/TM, 256, 73728>>>(x, h, Wih, Wout, bout);

    cudaFuncSetAttribute(gru_kernel,
                         cudaFuncAttributeMaxDynamicSharedMemorySize, SM_TOTAL);
    gru_kernel<<<16384/TM, NTHR, SM_TOTAL>>>(h, bout, out);
}

// round 16
// speedup vs baseline: 2.1807x; 1.0110x over previous
#include <cuda_runtime.h>
#include <cuda_fp16.h>
#include <cstdint>

#define T_IN 60
#define STEPS 30
#define TM 64
#define NTHR 512
#define WS 136               // weight image row stride (halfs)
#define BS2 72               // state tile row stride (halfs), k-major, conflict-free
#define TILE 18432u          // one state image: 128*72*2 bytes

#define SM_W    0u           // 544*136*2 = 147968
#define SM_S    147968u      // [buf][hi|lo][128][72] : 4 * 18432 = 73728
#define SM_BIA  221696u      // 512 floats
#define SM_TOTAL 223744u

// Weight image rows: [0,128) r = Whh_r + Wih_r*Wout ; [128,256) z merged;
// [256,384) nh = Whh_n ; [384,512) nx = Wih_n*Wout ; [512,544) Wout hi
__device__ __half g_Wimg[544*WS];
__device__ float  g_bias[512];
__device__ float  g_corr[16384*384];     // step-0 correction

__global__ void prep1(const float* Wih, const float* Whh, const float* Wout,
                      const float* bih, const float* bhh, const float* bout){
    int idx = blockIdx.x*blockDim.x + threadIdx.x;
    if (idx < 544*128){
        int row = idx >> 7, k = idx & 127;
        float v;
        if (row < 256){
            float d = 0.f;
            for (int i = 0; i < 32; i++) d += Wih[row*32+i]*Wout[i*128+k];
            v = Whh[row*128+k] + d;
        } else if (row < 384){
            v = Whh[row*128+k];
        } else if (row < 512){
            int j = row - 128;
            float d = 0.f;
            for (int i = 0; i < 32; i++) d += Wih[j*32+i]*Wout[i*128+k];
            v = d;
        } else {
            v = Wout[(row&31)*128 + k];
        }
        g_Wimg[row*WS + k] = __float2half_rn(v);
    } else if (idx < 544*128 + 384){
        int j = idx - 544*128;
        float bb = 0.f;
        for (int i = 0; i < 32; i++) bb += Wih[j*32+i]*bout[i];
        if (j < 256) g_bias[j] = bih[j] + bhh[j] + bb;
        else { g_bias[j] = bih[j] + bb; g_bias[j+128] = bhh[j]; }
    }
}

// corr[b][j] = Wih_j . (x0[b] - Wout*h0[b] - bout)
__global__ __launch_bounds__(256,1) void prep2(const float* x, const float* h0,
        const float* Wih, const float* Wout, const float* bout){
    extern __shared__ float s[];
    float* sWo = s; float* sWi = s + 4096; float* su = s + 16384;
    int tid = threadIdx.x; int m0 = blockIdx.x*TM;
    for (int i = tid; i < 4096;  i += 256) sWo[i] = Wout[i];
    for (int i = tid; i < 12288; i += 256) sWi[i] = Wih[i];
    __syncthreads();
    for (int q = tid; q < TM*32; q += 256){
        int b = q >> 5, i = q & 31;
        float a = x[((m0+b)*T_IN + 30)*32 + i] - bout[i];
        const float* hp = h0 + (m0+b)*128;
        for (int k = 0; k < 128; k++) a -= sWo[i*128+k]*hp[k];
        su[q] = a;
    }
    __syncthreads();
    for (int q = tid; q < TM*384; q += 256){
        int b = q / 384, j = q - b*384;
        float a = 0.f;
        const float* up = su + b*32;
        for (int i = 0; i < 32; i++) a += sWi[j*32+i]*up[i];
        g_corr[(m0+b)*384 + j] = a;
    }
}

__device__ __forceinline__ uint32_t su32(const void* p){
    uint32_t a; asm("{ .reg .u64 t; cvta.to.shared.u64 t, %1; cvt.u32.u64 %0, t; }":"=r"(a):"l"(p));
    return a;
}
__device__ __forceinline__ void cp16(uint32_t sd, const void* gs){
    asm volatile("cp.async.cg.shared.global [%0], [%1], 16;" :: "r"(sd), "l"(gs));
}
__device__ __forceinline__ void ldsm4(uint32_t* r, uint32_t a){
    asm volatile("ldmatrix.sync.aligned.m8n8.x4.shared.b16 {%0,%1,%2,%3}, [%4];"
        : "=r"(r[0]),"=r"(r[1]),"=r"(r[2]),"=r"(r[3]) : "r"(a));
}
__device__ __forceinline__ void ldsm4t(uint32_t* r, uint32_t a){
    asm volatile("ldmatrix.sync.aligned.m8n8.x4.trans.shared.b16 {%0,%1,%2,%3}, [%4];"
        : "=r"(r[0]),"=r"(r[1]),"=r"(r[2]),"=r"(r[3]) : "r"(a));
}
__device__ __forceinline__ void mma(float* c, const uint32_t* a, uint32_t b0, uint32_t b1){
    asm volatile("mma.sync.aligned.m16n8k16.row.col.f32.f16.f16.f32 "
        "{%0,%1,%2,%3},{%4,%5,%6,%7},{%8,%9},{%0,%1,%2,%3};"
        : "+f"(c[0]),"+f"(c[1]),"+f"(c[2]),"+f"(c[3])
        : "r"(a[0]),"r"(a[1]),"r"(a[2]),"r"(a[3]),"r"(b0),"r"(b1));
}
__device__ __forceinline__ float sigm(float v){ return __fdividef(1.f, 1.f + __expf(-v)); }
__device__ __forceinline__ float tanh_f(float v){
    float e = __expf(-2.f*fabsf(v));
    float t = __fdividef(1.f - e, 1.f + e);
    return v < 0.f ? -t : t;
}
__device__ __forceinline__ void put_hl(unsigned char* sm, uint32_t base, uint32_t off, float v){
    __half h = __float2half_rn(v);
    *(__half*)(sm + base + off) = h;
    *(__half*)(sm + base + TILE + off) = __float2half_rn(v - __half2float(h));
}

__global__ __launch_bounds__(NTHR,1)
void gru_kernel(const float* __restrict__ h0, const float* __restrict__ boutp,
                float* __restrict__ out){
    extern __shared__ unsigned char sm[];
    const uint32_t sb = su32(sm);
    const int tid = threadIdx.x, wid = tid>>5, lane = tid&31;
    const int m0 = blockIdx.x*TM;
    const int mt = wid&3, nt = wid>>2;
    const bool isy = (mt == nt);     // one y-warp per SMSP

    // resident weight image + biases
    for (int o = tid*16; o < 147968; o += NTHR*16)
        cp16(sb + SM_W + o, (const char*)g_Wimg + o);
    asm volatile("cp.async.commit_group;");
    for (int i = tid; i < 512; i += NTHR)
        ((float*)(sm + SM_BIA))[i] = g_bias[i];

    // initial state -> buffer 0, k-major [k][b]
    for (int q = tid; q < TM*128; q += NTHR){
        int b = q >> 7, k = q & 127;
        put_hl(sm, SM_S, (uint32_t)(k*BS2 + b)*2, h0[(m0+b)*128 + k]);
    }

    float bo[4];
    if (isy){
        #pragma unroll
        for (int q = 0; q < 4; q++) bo[q] = __ldg(boutp + (lane>>2) + q*8);
    }

    // ldmatrix bases
    const uint32_t bB0 = sb + SM_S +
        ((uint32_t)((lane&7) + ((lane>>3)&1)*8)*BS2 + (uint32_t)(nt*16 + (lane>>4)*8))*2;
    const uint32_t aG = sb + SM_W +
        ((uint32_t)((mt*32 + (lane&15))*WS) + (lane>>4)*8)*2;
    const uint32_t aY = sb + SM_W +
        ((uint32_t)((512 + (lane&15))*WS) + (lane>>4)*8)*2;

    asm volatile("cp.async.wait_all;" ::: "memory");
    __syncthreads();

    for (int t = 0; t < STEPS; t++){
        const uint32_t cur = (uint32_t)(t & 1);
        const uint32_t bB  = bB0 + cur*(2*TILE);
        const uint32_t nxtb = SM_S + (cur^1u)*(2*TILE);

        float acc[4][2][2][4] = {};
        float yac[2][2][4] = {};
        #pragma unroll
        for (int kk = 0; kk < 8; kk++){
            const uint32_t bko = (uint32_t)kk*16*BS2*2;   // advance 16 k-rows
            const uint32_t ako = (uint32_t)kk*32;
            uint32_t bh[4], bl[4];
            ldsm4t(bh, bB + bko);
            ldsm4t(bl, bB + TILE + bko);
            #pragma unroll
            for (int g = 0; g < 4; g++){
                uint32_t a0[4], a1[4];
                ldsm4(a0, aG + g*34816u + ako);
                ldsm4(a1, aG + g*34816u + 4352u + ako);
                mma(acc[g][0][0], a0, bh[0], bh[1]);
                mma(acc[g][0][1], a0, bh[2], bh[3]);
                mma(acc[g][1][0], a1, bh[0], bh[1]);
                mma(acc[g][1][1], a1, bh[2], bh[3]);
                mma(acc[g][0][0], a0, bl[0], bl[1]);
                mma(acc[g][0][1], a0, bl[2], bl[3]);
                mma(acc[g][1][0], a1, bl[0], bl[1]);
                mma(acc[g][1][1], a1, bl[2], bl[3]);
            }
            if (isy){
                uint32_t yh0[4], yh1[4];
                ldsm4(yh0, aY + ako);
                ldsm4(yh1, aY + 4352u + ako);
                mma(yac[0][0], yh0, bh[0], bh[1]); mma(yac[0][1], yh0, bh[2], bh[3]);
                mma(yac[1][0], yh1, bh[0], bh[1]); mma(yac[1][1], yh1, bh[2], bh[3]);
                mma(yac[0][0], yh0, bl[0], bl[1]); mma(yac[0][1], yh0, bl[2], bl[3]);
                mma(yac[1][0], yh1, bl[0], bl[1]); mma(yac[1][1], yh1, bl[2], bl[3]);
            }
        }

        // epilogue writes the OTHER buffer — no barrier needed before it
        const float* gb = (const float*)(sm + SM_BIA);
        #pragma unroll
        for (int mi = 0; mi < 2; mi++)
        #pragma unroll
        for (int ni = 0; ni < 2; ni++)
        #pragma unroll
        for (int ep = 0; ep < 2; ep++){
            int j = mt*32 + (lane>>2) + (mi*2 + ep)*8;
            int b = nt*16 + ni*8 + (lane&3)*2;
            float ar0 = acc[0][mi][ni][ep*2],   ar1 = acc[0][mi][ni][ep*2+1];
            float az0 = acc[1][mi][ni][ep*2],   az1 = acc[1][mi][ni][ep*2+1];
            float ah0 = acc[2][mi][ni][ep*2],   ah1 = acc[2][mi][ni][ep*2+1];
            float ax0 = acc[3][mi][ni][ep*2],   ax1 = acc[3][mi][ni][ep*2+1];
            if (t == 0){
                const float* c0 = g_corr + (m0+b)*384 + j;
                const float* c1 = c0 + 384;
                ar0 += c0[0]; az0 += c0[128]; ax0 += c0[256];
                ar1 += c1[0]; az1 += c1[128]; ax1 += c1[256];
            }
            uint32_t so = (uint32_t)(j*BS2 + b)*2;
            __half2 hh = *(__half2*)(sm + SM_S + cur*(2*TILE) + so);
            __half2 hl = *(__half2*)(sm + SM_S + cur*(2*TILE) + TILE + so);
            float hv0 = __low2float(hh)  + __low2float(hl);
            float hv1 = __high2float(hh) + __high2float(hl);
            float bj_r = gb[j], bj_z = gb[128+j], bj_x = gb[256+j], bj_h = gb[384+j];
            float r0 = sigm(ar0 + bj_r), r1 = sigm(ar1 + bj_r);
            float z0 = sigm(az0 + bj_z), z1 = sigm(az1 + bj_z);
            float n0 = tanh_f(ax0 + bj_x + r0*(ah0 + bj_h));
            float n1 = tanh_f(ax1 + bj_x + r1*(ah1 + bj_h));
            float o0 = n0 + z0*(hv0 - n0);
            float o1 = n1 + z1*(hv1 - n1);
            __half p0 = __float2half_rn(o0), p1 = __float2half_rn(o1);
            *(__half2*)(sm + nxtb + so) = __halves2half2(p0, p1);
            *(__half2*)(sm + nxtb + TILE + so) = __halves2half2(
                __float2half_rn(o0 - __half2float(p0)),
                __float2half_rn(o1 - __half2float(p1)));
        }
        if (isy && t > 0){
            #pragma unroll
            for (int mi = 0; mi < 2; mi++)
            #pragma unroll
            for (int ni = 0; ni < 2; ni++)
            #pragma unroll
            for (int e = 0; e < 4; e++){
                int i = (lane>>2) + (mi*2 + (e>>1))*8;
                int b = nt*16 + ni*8 + (lane&3)*2 + (e&1);
                out[((m0+b)*STEPS + (t-1))*32 + i] = yac[mi][ni][e] + bo[mi*2 + (e>>1)];
            }
        }
        __syncthreads();     // nxt-buffer writes visible before next step's reads
    }

    // final y_29 = Wout * h_30 (h after step 29, in buffer 0)
    if (isy){
        float yac[2][2][4] = {};
        #pragma unroll
        for (int kk = 0; kk < 8; kk++){
            const uint32_t bko = (uint32_t)kk*16*BS2*2;
            const uint32_t ako = (uint32_t)kk*32;
            uint32_t bh[4], bl[4], yh0[4], yh1[4];
            ldsm4t(bh, bB0 + bko);
            ldsm4t(bl, bB0 + TILE + bko);
            ldsm4(yh0, aY + ako);
            ldsm4(yh1, aY + 4352u + ako);
            mma(yac[0][0], yh0, bh[0], bh[1]); mma(yac[0][1], yh0, bh[2], bh[3]);
            mma(yac[1][0], yh1, bh[0], bh[1]); mma(yac[1][1], yh1, bh[2], bh[3]);
            mma(yac[0][0], yh0, bl[0], bl[1]); mma(yac[0][1], yh0, bl[2], bl[3]);
            mma(yac[1][0], yh1, bl[0], bl[1]); mma(yac[1][1], yh1, bl[2], bl[3]);
        }
        #pragma unroll
        for (int mi = 0; mi < 2; mi++)
        #pragma unroll
        for (int ni = 0; ni < 2; ni++)
        #pragma unroll
        for (int e = 0; e < 4; e++){
            int i = (lane>>2) + (mi*2 + (e>>1))*8;
            int b = nt*16 + ni*8 + (lane&3)*2 + (e&1);
            out[((m0+b)*STEPS + 29)*32 + i] = yac[mi][ni][e] + bo[mi*2 + (e>>1)];
        }
    }
}

extern "C" void kernel_launch(void* const* d_in, const int* in_sizes, int n_in,
                              void* d_out, int out_size){
    const float* x    = (const float*)d_in[0];
    const float* h    = (const float*)d_in[1];
    const float* Wih  = (const float*)d_in[2];
    const float* Whh  = (const float*)d_in[3];
    const float* bih  = (const float*)d_in[4];
    const float* bhh  = (const float*)d_in[5];
    const float* Wout = (const float*)d_in[6];
    const float* bout = (const float*)d_in[7];
    float* out = (float*)d_out;

    prep1<<<(544*128 + 384 + 255)/256, 256>>>(Wih, Whh, Wout, bih, bhh, bout);

    cudaFuncSetAttribute(prep2, cudaFuncAttributeMaxDynamicSharedMemorySize, 73728);
    prep2<<<16384/TM, 256, 73728>>>(x, h, Wih, Wout, bout);

    cudaFuncSetAttribute(gru_kernel,
                         cudaFuncAttributeMaxDynamicSharedMemorySize, SM_TOTAL);
    gru_kernel<<<16384/TM, NTHR, SM_TOTAL>>>(h, bout, out);
}